// round 4
// baseline (speedup 1.0000x reference)
#include <cuda_runtime.h>

// Problem constants
#define B_   16
#define T_   28
#define NF   448      // B_*T_
#define HW   1024     // 32*32
#define F_   64

// -------- static scratch (allocation-free requirement) --------
constexpr size_t XG_SZ = (size_t)NF * HW * 192;   // per direction
constexpr size_t X0_SZ = (size_t)NF * HW * 128;
constexpr size_t HS_SZ = (size_t)B_ * HW * F_;    // per direction

__device__ float g_xg[2][XG_SZ];   // input-gate activations (reused by both layers)
__device__ float g_x0[X0_SZ];      // layer-0 bidir output
__device__ float g_xr[X0_SZ];      // x0 + layer-1 bidir output
__device__ float g_h [2][HS_SZ];   // GRU hidden state per direction
__device__ float g_z [2][HS_SZ];   // z gate scratch
__device__ float g_rh[2][HS_SZ];   // r*h scratch

// ---- packed fp32x2 helpers (sm_103a; ptxas never emits these from C++) ----
__device__ __forceinline__ void ffma2(unsigned long long& d,
                                      unsigned long long a,
                                      unsigned long long b)
{
    asm("fma.rn.f32x2 %0, %1, %2, %0;" : "+l"(d) : "l"(a), "l"(b));
}
__device__ __forceinline__ unsigned long long bcast2(float v)
{
    unsigned long long r;
    asm("mov.b64 %0, {%1, %1};" : "=l"(r) : "f"(v));
    return r;
}
__device__ __forceinline__ float2 unpk(unsigned long long a)
{
    return make_float2(__uint_as_float((unsigned)a),
                       __uint_as_float((unsigned)(a >> 32)));
}

// ============================================================================
// conv2core: tiled 3x3 SAME conv, v2.
// Block = 256 threads. Tile = 2 output rows (y0, y0+1) x 32 px x CO_TILE couts.
// Thread: p = tid&15 -> (row = p>>3, px0 = (p&7)*4), g = tid>>4 (16 cout groups).
// Each thread: 4 pixels x TC couts (TC = CO_TILE/16), packed f32x2 accumulators.
// s_in layout: [c(8)][irow(4)][35]  (row-stride 35 == 3 mod 32 -> conflict-free)
//   col j of the image stored at col j+1; cols 0 and 33/34 are zero padding.
// s_w  layout: [tap(9)][c(8)][CO_TILE]
// acc: unsigned long long [4][TC/2], pairs of adjacent couts.
// ============================================================================
template<int CIN, int CO_TILE>
__device__ __forceinline__ void conv2core(
    const float* __restrict__ in, int in_stride,
    const float* __restrict__ w, int w_cin_total, int w_co_stride,
    int ci_off, int co_base, int y0,
    unsigned long long* __restrict__ acc,
    float* __restrict__ s_in, float* __restrict__ s_w)
{
    constexpr int TC  = CO_TILE / 16;
    constexpr int TC2 = TC / 2;
    const int tid = threadIdx.x;
    const int p   = tid & 15;
    const int row = p >> 3;
    const int px0 = (p & 7) * 4;
    const int g   = tid >> 4;

    // zero the input tile once (establishes padding cols 0 and 33/34)
    for (int i = tid; i < 8 * 4 * 35; i += 256) s_in[i] = 0.f;
    __syncthreads();

    for (int cc = 0; cc < CIN; cc += 8) {
        // ---- load input tile: 4 rows x 32 px x 8 ch, 1 float4 per thread ----
        {
            int c4  = tid & 1;
            int px  = (tid >> 1) & 31;
            int irw = tid >> 6;               // 0..3
            int gy  = y0 - 1 + irw;
            float4 v = make_float4(0.f, 0.f, 0.f, 0.f);
            if (gy >= 0 && gy < 32)
                v = *reinterpret_cast<const float4*>(
                        in + (size_t)(gy * 32 + px) * in_stride + cc + c4 * 4);
            float* sp = s_in + ((c4 * 4) * 4 + irw) * 35 + px + 1;
            sp[0]       = v.x;     // c = c4*4+0
            sp[4 * 35]  = v.y;     // c = c4*4+1
            sp[8 * 35]  = v.z;
            sp[12 * 35] = v.w;
        }
        // ---- load weight tile: 9 taps x 8 ch x CO_TILE ----
        constexpr int CO4 = CO_TILE / 4;
        constexpr int NW4 = 9 * 8 * CO4;
        for (int idx = tid; idx < NW4; idx += 256) {
            int co4  = idx % CO4;
            int rest = idx / CO4;
            int c    = rest & 7;
            int tap  = rest >> 3;
            float4 v = *reinterpret_cast<const float4*>(
                w + (size_t)(tap * w_cin_total + ci_off + cc + c) * w_co_stride
                  + co_base + co4 * 4);
            *reinterpret_cast<float4*>(s_w + (tap * 8 + c) * CO_TILE + co4 * 4) = v;
        }
        __syncthreads();

        // ---- compute ----
        #pragma unroll
        for (int c = 0; c < 8; c++) {
            #pragma unroll
            for (int ky = 0; ky < 3; ky++) {
                const float* ip = s_in + (c * 4 + row + ky) * 35 + px0;
                unsigned long long in2[6];
                #pragma unroll
                for (int k = 0; k < 6; k++) in2[k] = bcast2(ip[k]);
                #pragma unroll
                for (int kx = 0; kx < 3; kx++) {
                    const float* wp = s_w + ((ky * 3 + kx) * 8 + c) * CO_TILE + g * TC;
                    if (TC2 >= 2) {
                        #pragma unroll
                        for (int j4 = 0; j4 < TC2 / 2; j4++) {
                            ulonglong2 wv = reinterpret_cast<const ulonglong2*>(wp)[j4];
                            #pragma unroll
                            for (int i = 0; i < 4; i++) {
                                ffma2(acc[i * TC2 + j4 * 2 + 0], in2[i + kx], wv.x);
                                ffma2(acc[i * TC2 + j4 * 2 + 1], in2[i + kx], wv.y);
                            }
                        }
                    } else {
                        unsigned long long wv =
                            *reinterpret_cast<const unsigned long long*>(wp);
                        #pragma unroll
                        for (int i = 0; i < 4; i++)
                            ffma2(acc[i], in2[i + kx], wv);
                    }
                }
            }
        }
        __syncthreads();
    }
}

// ============================================================================
// Batched input-gate conv: xg[dir] = conv3x3(in, wx) + b over all 448 frames.
// grid: x = 16 row-pairs, y = frame, z = cout tile (3 x 64).  TC = 4.
// ============================================================================
template<int CIN>
__global__ void __launch_bounds__(256) k_xg(
    const float* __restrict__ xin, const float* __restrict__ w,
    const float* __restrict__ bias, int dir, int use_x0)
{
    const int y0 = blockIdx.x * 2;
    const int n  = blockIdx.y;
    const int co_base = blockIdx.z * 64;
    __shared__ __align__(16) float s_in[8 * 4 * 35];
    __shared__ __align__(16) float s_w[9 * 8 * 64];
    const float* in = use_x0 ? (g_x0 + (size_t)n * HW * 128)
                             : (xin + (size_t)n * HW * CIN);
    const int in_stride = use_x0 ? 128 : CIN;
    unsigned long long acc[4 * 2];
    #pragma unroll
    for (int j = 0; j < 8; j++) acc[j] = 0ull;
    conv2core<CIN, 64>(in, in_stride, w, CIN, 192, 0, co_base, y0, acc, s_in, s_w);

    const int p = threadIdx.x & 15, g = threadIdx.x >> 4;
    const int row = p >> 3, px0 = (p & 7) * 4;
    const float* bp = bias + co_base + g * 4;
    float b0 = bp[0], b1v = bp[1], b2 = bp[2], b3 = bp[3];
    #pragma unroll
    for (int i = 0; i < 4; i++) {
        int pixel = (y0 + row) * 32 + px0 + i;
        float2 a0 = unpk(acc[i * 2 + 0]);
        float2 a1 = unpk(acc[i * 2 + 1]);
        float4 v = make_float4(a0.x + b0, a0.y + b1v, a1.x + b2, a1.y + b3);
        *reinterpret_cast<float4*>(
            g_xg[dir] + ((size_t)n * HW + pixel) * 192 + co_base + g * 4) = v;
    }
}

// ============================================================================
// Recurrence kernel A: gh = conv3x3(h, wh[...,0:128]); z/r sigmoids; writes
// z and r*h.  grid: x = 16 row-pairs, y = B, z = dir.  CO=128, TC=8.
// ============================================================================
__global__ void __launch_bounds__(256) k_gate(
    const float* __restrict__ whf, const float* __restrict__ whb, int s)
{
    const int y0 = blockIdx.x * 2, b = blockIdx.y, dir = blockIdx.z;
    const int t = dir ? (T_ - 1 - s) : s;
    const int frame = b * T_ + t;
    const float* w = dir ? whb : whf;
    __shared__ __align__(16) float s_in[8 * 4 * 35];
    __shared__ __align__(16) float s_w[9 * 8 * 128];
    unsigned long long acc[4 * 4];
    #pragma unroll
    for (int j = 0; j < 16; j++) acc[j] = 0ull;
    conv2core<64, 128>(g_h[dir] + (size_t)b * HW * 64, 64,
                       w, 64, 192, 0, 0, y0, acc, s_in, s_w);

    const int p = threadIdx.x & 15, g = threadIdx.x >> 4;
    const int row = p >> 3, px0 = (p & 7) * 4;
    #pragma unroll
    for (int i = 0; i < 4; i++) {
        int pixel = (y0 + row) * 32 + px0 + i;
        const float* xgp = g_xg[dir] + ((size_t)frame * HW + pixel) * 192 + g * 8;
        float4 x0v = *reinterpret_cast<const float4*>(xgp);
        float4 x1v = *reinterpret_cast<const float4*>(xgp + 4);
        float xv[8] = {x0v.x, x0v.y, x0v.z, x0v.w, x1v.x, x1v.y, x1v.z, x1v.w};
        float sg[8];
        #pragma unroll
        for (int j2 = 0; j2 < 4; j2++) {
            float2 a = unpk(acc[i * 4 + j2]);
            sg[j2 * 2 + 0] = 1.f / (1.f + __expf(-(xv[j2 * 2 + 0] + a.x)));
            sg[j2 * 2 + 1] = 1.f / (1.f + __expf(-(xv[j2 * 2 + 1] + a.y)));
        }
        const int pix = (b * HW + pixel) * 64;
        if (g < 8) {       // z gates, co = g*8..g*8+7
            float* zp = g_z[dir] + pix + g * 8;
            *reinterpret_cast<float4*>(zp)     = make_float4(sg[0], sg[1], sg[2], sg[3]);
            *reinterpret_cast<float4*>(zp + 4) = make_float4(sg[4], sg[5], sg[6], sg[7]);
        } else {           // r gates -> r*h, co' = (g-8)*8..+7
            const float* hp = g_h[dir] + pix + (g - 8) * 8;
            float4 h0 = *reinterpret_cast<const float4*>(hp);
            float4 h1 = *reinterpret_cast<const float4*>(hp + 4);
            float* rp = g_rh[dir] + pix + (g - 8) * 8;
            *reinterpret_cast<float4*>(rp) =
                make_float4(sg[0] * h0.x, sg[1] * h0.y, sg[2] * h0.z, sg[3] * h0.w);
            *reinterpret_cast<float4*>(rp + 4) =
                make_float4(sg[4] * h1.x, sg[5] * h1.y, sg[6] * h1.z, sg[7] * h1.w);
        }
    }
}

// ============================================================================
// Recurrence kernel B: c = conv3x3(r*h, wh[...,128:192]); hh = tanh(xg+c);
// h = z*h + (1-z)*hh; write h and per-timestep output.  CO=64, TC=4.
// ============================================================================
__global__ void __launch_bounds__(256) k_update(
    const float* __restrict__ whf, const float* __restrict__ whb, int s, int layer1)
{
    const int y0 = blockIdx.x * 2, b = blockIdx.y, dir = blockIdx.z;
    const int t = dir ? (T_ - 1 - s) : s;
    const int frame = b * T_ + t;
    const float* w = dir ? whb : whf;
    __shared__ __align__(16) float s_in[8 * 4 * 35];
    __shared__ __align__(16) float s_w[9 * 8 * 64];
    unsigned long long acc[4 * 2];
    #pragma unroll
    for (int j = 0; j < 8; j++) acc[j] = 0ull;
    conv2core<64, 64>(g_rh[dir] + (size_t)b * HW * 64, 64,
                      w, 64, 192, 0, 128, y0, acc, s_in, s_w);

    const int p = threadIdx.x & 15, g = threadIdx.x >> 4;
    const int row = p >> 3, px0 = (p & 7) * 4;
    #pragma unroll
    for (int i = 0; i < 4; i++) {
        int pixel = (y0 + row) * 32 + px0 + i;
        const float* xgp = g_xg[dir] + ((size_t)frame * HW + pixel) * 192 + 128 + g * 4;
        float4 xv = *reinterpret_cast<const float4*>(xgp);
        float2 a0 = unpk(acc[i * 2 + 0]);
        float2 a1 = unpk(acc[i * 2 + 1]);
        const int pix = (b * HW + pixel) * 64 + g * 4;
        float4 zv = *reinterpret_cast<const float4*>(g_z[dir] + pix);
        float4 hv = *reinterpret_cast<const float4*>(g_h[dir] + pix);
        float hh0 = tanhf(xv.x + a0.x);
        float hh1 = tanhf(xv.y + a0.y);
        float hh2 = tanhf(xv.z + a1.x);
        float hh3 = tanhf(xv.w + a1.y);
        float4 hn = make_float4(zv.x * hv.x + (1.f - zv.x) * hh0,
                                zv.y * hv.y + (1.f - zv.y) * hh1,
                                zv.z * hv.z + (1.f - zv.z) * hh2,
                                zv.w * hv.w + (1.f - zv.w) * hh3);
        *reinterpret_cast<float4*>(g_h[dir] + pix) = hn;
        const size_t opix = ((size_t)frame * HW + pixel) * 128 + dir * 64 + g * 4;
        if (layer1) {
            float4 xo = *reinterpret_cast<const float4*>(g_x0 + opix);
            *reinterpret_cast<float4*>(g_xr + opix) =
                make_float4(xo.x + hn.x, xo.y + hn.y, xo.z + hn.z, xo.w + hn.w);
        } else {
            *reinterpret_cast<float4*>(g_x0 + opix) = hn;
        }
    }
}

// ============================================================================
// Final fused head: conv3x3(concat(xr, x0), w_conv1)+b1 -> 1x1 conv + b_out ->
// relu.  CO=32, TC=2.  grid: x = 16 row-pairs, y = frame.
// ============================================================================
__global__ void __launch_bounds__(256) k_final(
    const float* __restrict__ w1, const float* __restrict__ b1,
    const float* __restrict__ wo, const float* __restrict__ bo,
    float* __restrict__ out)
{
    const int y0 = blockIdx.x * 2, n = blockIdx.y;
    __shared__ __align__(16) float s_in[8 * 4 * 35];
    __shared__ __align__(16) float s_w[9 * 8 * 32];
    __shared__ float s_red[16][64];
    unsigned long long acc[4];
    #pragma unroll
    for (int j = 0; j < 4; j++) acc[j] = 0ull;
    conv2core<128, 32>(g_xr + (size_t)n * HW * 128, 128, w1, 256, 32, 0,   0, y0, acc, s_in, s_w);
    conv2core<128, 32>(g_x0 + (size_t)n * HW * 128, 128, w1, 256, 32, 128, 0, y0, acc, s_in, s_w);

    const int p = threadIdx.x & 15, g = threadIdx.x >> 4;
    const int row = p >> 3, px0 = (p & 7) * 4;
    float bb0 = b1[g * 2], bb1 = b1[g * 2 + 1];
    float ww0 = wo[g * 2], ww1 = wo[g * 2 + 1];
    #pragma unroll
    for (int i = 0; i < 4; i++) {
        float2 a = unpk(acc[i]);
        s_red[g][row * 32 + px0 + i] = (a.x + bb0) * ww0 + (a.y + bb1) * ww1;
    }
    __syncthreads();
    if (threadIdx.x < 64) {
        int lp = threadIdx.x;   // local pixel 0..63
        float sum = bo[0];
        #pragma unroll
        for (int k = 0; k < 16; k++) sum += s_red[k][lp];
        out[(size_t)n * HW + y0 * 32 + lp] = fmaxf(sum, 0.f);
    }
}

__global__ void k_zero_h()
{
    int i = blockIdx.x * 256 + threadIdx.x;
    if (i < 2 * B_ * HW * F_) (&g_h[0][0])[i] = 0.f;
}

// ============================================================================
extern "C" void kernel_launch(void* const* d_in, const int* in_sizes, int n_in,
                              void* d_out, int out_size)
{
    (void)in_sizes; (void)n_in; (void)out_size;
    const float* x     = (const float*)d_in[0];
    const float* wx_f0 = (const float*)d_in[1];
    const float* wh_f0 = (const float*)d_in[2];
    const float* b_f0  = (const float*)d_in[3];
    const float* wx_b0 = (const float*)d_in[4];
    const float* wh_b0 = (const float*)d_in[5];
    const float* b_b0  = (const float*)d_in[6];
    const float* wx_f1 = (const float*)d_in[7];
    const float* wh_f1 = (const float*)d_in[8];
    const float* b_f1  = (const float*)d_in[9];
    const float* wx_b1 = (const float*)d_in[10];
    const float* wh_b1 = (const float*)d_in[11];
    const float* b_b1  = (const float*)d_in[12];
    const float* w1    = (const float*)d_in[13];
    const float* b1    = (const float*)d_in[14];
    const float* wo    = (const float*)d_in[15];
    const float* bo    = (const float*)d_in[16];
    float* out = (float*)d_out;

    dim3 blk(256);

    // ---- layer 0 ----
    k_xg<24><<<dim3(16, NF, 3), blk>>>(x, wx_f0, b_f0, 0, 0);
    k_xg<24><<<dim3(16, NF, 3), blk>>>(x, wx_b0, b_b0, 1, 0);
    k_zero_h<<<(2 * B_ * HW * F_ + 255) / 256, blk>>>();
    for (int s = 0; s < T_; s++) {
        k_gate  <<<dim3(16, B_, 2), blk>>>(wh_f0, wh_b0, s);
        k_update<<<dim3(16, B_, 2), blk>>>(wh_f0, wh_b0, s, 0);
    }

    // ---- layer 1 ----
    k_xg<128><<<dim3(16, NF, 3), blk>>>(nullptr, wx_f1, b_f1, 0, 1);
    k_xg<128><<<dim3(16, NF, 3), blk>>>(nullptr, wx_b1, b_b1, 1, 1);
    k_zero_h<<<(2 * B_ * HW * F_ + 255) / 256, blk>>>();
    for (int s = 0; s < T_; s++) {
        k_gate  <<<dim3(16, B_, 2), blk>>>(wh_f1, wh_b1, s);
        k_update<<<dim3(16, B_, 2), blk>>>(wh_f1, wh_b1, s, 1);
    }

    // ---- fused head ----
    k_final<<<dim3(16, NF), blk>>>(w1, b1, wo, bo, out);
}

// round 11
// speedup vs baseline: 1.0546x; 1.0546x over previous
#include <cuda_runtime.h>
#include <cstdint>

#define B_   16
#define T_   28
#define NF   448
#define HW   1024
#define F_   64

constexpr size_t XG_SZ = (size_t)NF * HW * 192;
constexpr size_t X0_SZ = (size_t)NF * HW * 128;
constexpr size_t HS_SZ = (size_t)B_ * HW * F_;

__device__ float g_xg[2][XG_SZ];
__device__ float g_x0[X0_SZ];
__device__ float g_xr[X0_SZ];
__device__ float g_h [2][HS_SZ];
__device__ float g_z [2][HS_SZ];
__device__ float g_rh[2][HS_SZ];

// pre-split tf32 hi/lo weights for the layer-1 xg MMA, plain layout:
// [set][it(36)][split(2)][k(32)][n(192)]
constexpr size_t ITSZ  = 2 * 32 * 192;      // 12288 floats per (tap,kc)
constexpr size_t SETSZ = 36 * ITSZ;
__device__ float g_bpre[2 * SETSZ];

// ---- packed fp32x2 helpers ----
__device__ __forceinline__ void ffma2(unsigned long long& d, unsigned long long a,
                                      unsigned long long b)
{ asm("fma.rn.f32x2 %0, %1, %2, %0;" : "+l"(d) : "l"(a), "l"(b)); }
__device__ __forceinline__ unsigned long long bcast2(float v)
{ unsigned long long r; asm("mov.b64 %0, {%1, %1};" : "=l"(r) : "f"(v)); return r; }
__device__ __forceinline__ float2 unpk(unsigned long long a)
{ return make_float2(__uint_as_float((unsigned)a), __uint_as_float((unsigned)(a >> 32))); }

// ---- tf32 helpers (sm_80+ PTX, legal on compute_103) ----
__device__ __forceinline__ uint32_t f2tf(float v)
{ uint32_t r; asm("cvt.rna.tf32.f32 %0, %1;" : "=r"(r) : "f"(v)); return r; }

__device__ __forceinline__ void mma8(float* c, const uint32_t* a,
                                     uint32_t b0, uint32_t b1)
{
    asm("mma.sync.aligned.m16n8k8.row.col.f32.tf32.tf32.f32 "
        "{%0,%1,%2,%3}, {%4,%5,%6,%7}, {%8,%9}, {%0,%1,%2,%3};"
        : "+f"(c[0]), "+f"(c[1]), "+f"(c[2]), "+f"(c[3])
        : "r"(a[0]), "r"(a[1]), "r"(a[2]), "r"(a[3]), "r"(b0), "r"(b1));
}

// ============================================================================
// conv2core (FFMA2 path) — unchanged from the 21.3ms baseline
// ============================================================================
template<int CIN, int CO_TILE>
__device__ __forceinline__ void conv2core(
    const float* __restrict__ in, int in_stride,
    const float* __restrict__ w, int w_cin_total, int w_co_stride,
    int ci_off, int co_base, int y0,
    unsigned long long* __restrict__ acc,
    float* __restrict__ s_in, float* __restrict__ s_w)
{
    constexpr int TC  = CO_TILE / 16;
    constexpr int TC2 = TC / 2;
    const int tid = threadIdx.x;
    const int p   = tid & 15;
    const int row = p >> 3;
    const int px0 = (p & 7) * 4;
    const int g   = tid >> 4;

    for (int i = tid; i < 8 * 4 * 35; i += 256) s_in[i] = 0.f;
    __syncthreads();

    for (int cc = 0; cc < CIN; cc += 8) {
        {
            int c4  = tid & 1;
            int px  = (tid >> 1) & 31;
            int irw = tid >> 6;
            int gy  = y0 - 1 + irw;
            float4 v = make_float4(0.f, 0.f, 0.f, 0.f);
            if (gy >= 0 && gy < 32)
                v = *reinterpret_cast<const float4*>(
                        in + (size_t)(gy * 32 + px) * in_stride + cc + c4 * 4);
            float* sp = s_in + ((c4 * 4) * 4 + irw) * 35 + px + 1;
            sp[0] = v.x; sp[4 * 35] = v.y; sp[8 * 35] = v.z; sp[12 * 35] = v.w;
        }
        constexpr int CO4 = CO_TILE / 4;
        constexpr int NW4 = 9 * 8 * CO4;
        for (int idx = tid; idx < NW4; idx += 256) {
            int co4  = idx % CO4;
            int rest = idx / CO4;
            int c    = rest & 7;
            int tap  = rest >> 3;
            float4 v = *reinterpret_cast<const float4*>(
                w + (size_t)(tap * w_cin_total + ci_off + cc + c) * w_co_stride
                  + co_base + co4 * 4);
            *reinterpret_cast<float4*>(s_w + (tap * 8 + c) * CO_TILE + co4 * 4) = v;
        }
        __syncthreads();

        #pragma unroll
        for (int c = 0; c < 8; c++) {
            #pragma unroll
            for (int ky = 0; ky < 3; ky++) {
                const float* ip = s_in + (c * 4 + row + ky) * 35 + px0;
                unsigned long long in2[6];
                #pragma unroll
                for (int k = 0; k < 6; k++) in2[k] = bcast2(ip[k]);
                #pragma unroll
                for (int kx = 0; kx < 3; kx++) {
                    const float* wp = s_w + ((ky * 3 + kx) * 8 + c) * CO_TILE + g * TC;
                    if (TC2 >= 2) {
                        #pragma unroll
                        for (int j4 = 0; j4 < TC2 / 2; j4++) {
                            ulonglong2 wv = reinterpret_cast<const ulonglong2*>(wp)[j4];
                            #pragma unroll
                            for (int i = 0; i < 4; i++) {
                                ffma2(acc[i * TC2 + j4 * 2 + 0], in2[i + kx], wv.x);
                                ffma2(acc[i * TC2 + j4 * 2 + 1], in2[i + kx], wv.y);
                            }
                        }
                    } else {
                        unsigned long long wv =
                            *reinterpret_cast<const unsigned long long*>(wp);
                        #pragma unroll
                        for (int i = 0; i < 4; i++)
                            ffma2(acc[i], in2[i + kx], wv);
                    }
                }
            }
        }
        __syncthreads();
    }
}

// ---- k_xg (FFMA2) — layer-0 only ----
template<int CIN>
__global__ void __launch_bounds__(256) k_xg(
    const float* __restrict__ xin, const float* __restrict__ w,
    const float* __restrict__ bias, int dir)
{
    const int y0 = blockIdx.x * 2;
    const int n  = blockIdx.y;
    const int co_base = blockIdx.z * 64;
    __shared__ __align__(16) float s_in[8 * 4 * 35];
    __shared__ __align__(16) float s_w[9 * 8 * 64];
    const float* in = xin + (size_t)n * HW * CIN;
    unsigned long long acc[4 * 2];
    #pragma unroll
    for (int j = 0; j < 8; j++) acc[j] = 0ull;
    conv2core<CIN, 64>(in, CIN, w, CIN, 192, 0, co_base, y0, acc, s_in, s_w);

    const int p = threadIdx.x & 15, g = threadIdx.x >> 4;
    const int row = p >> 3, px0 = (p & 7) * 4;
    const float* bp = bias + co_base + g * 4;
    float b0 = bp[0], b1v = bp[1], b2 = bp[2], b3 = bp[3];
    #pragma unroll
    for (int i = 0; i < 4; i++) {
        int pixel = (y0 + row) * 32 + px0 + i;
        float2 a0 = unpk(acc[i * 2 + 0]);
        float2 a1 = unpk(acc[i * 2 + 1]);
        float4 v = make_float4(a0.x + b0, a0.y + b1v, a1.x + b2, a1.y + b3);
        *reinterpret_cast<float4*>(
            g_xg[dir] + ((size_t)n * HW + pixel) * 192 + co_base + g * 4) = v;
    }
}

// ---- k_gate — unchanged ----
__global__ void __launch_bounds__(256) k_gate(
    const float* __restrict__ whf, const float* __restrict__ whb, int s)
{
    const int y0 = blockIdx.x * 2, b = blockIdx.y, dir = blockIdx.z;
    const int t = dir ? (T_ - 1 - s) : s;
    const int frame = b * T_ + t;
    const float* w = dir ? whb : whf;
    __shared__ __align__(16) float s_in[8 * 4 * 35];
    __shared__ __align__(16) float s_w[9 * 8 * 128];
    unsigned long long acc[4 * 4];
    #pragma unroll
    for (int j = 0; j < 16; j++) acc[j] = 0ull;
    conv2core<64, 128>(g_h[dir] + (size_t)b * HW * 64, 64,
                       w, 64, 192, 0, 0, y0, acc, s_in, s_w);

    const int p = threadIdx.x & 15, g = threadIdx.x >> 4;
    const int row = p >> 3, px0 = (p & 7) * 4;
    #pragma unroll
    for (int i = 0; i < 4; i++) {
        int pixel = (y0 + row) * 32 + px0 + i;
        const float* xgp = g_xg[dir] + ((size_t)frame * HW + pixel) * 192 + g * 8;
        float4 x0v = *reinterpret_cast<const float4*>(xgp);
        float4 x1v = *reinterpret_cast<const float4*>(xgp + 4);
        float xv[8] = {x0v.x, x0v.y, x0v.z, x0v.w, x1v.x, x1v.y, x1v.z, x1v.w};
        float sg[8];
        #pragma unroll
        for (int j2 = 0; j2 < 4; j2++) {
            float2 a = unpk(acc[i * 4 + j2]);
            sg[j2 * 2 + 0] = 1.f / (1.f + __expf(-(xv[j2 * 2 + 0] + a.x)));
            sg[j2 * 2 + 1] = 1.f / (1.f + __expf(-(xv[j2 * 2 + 1] + a.y)));
        }
        const int pix = (b * HW + pixel) * 64;
        if (g < 8) {
            float* zp = g_z[dir] + pix + g * 8;
            *reinterpret_cast<float4*>(zp)     = make_float4(sg[0], sg[1], sg[2], sg[3]);
            *reinterpret_cast<float4*>(zp + 4) = make_float4(sg[4], sg[5], sg[6], sg[7]);
        } else {
            const float* hp = g_h[dir] + pix + (g - 8) * 8;
            float4 h0 = *reinterpret_cast<const float4*>(hp);
            float4 h1 = *reinterpret_cast<const float4*>(hp + 4);
            float* rp = g_rh[dir] + pix + (g - 8) * 8;
            *reinterpret_cast<float4*>(rp) =
                make_float4(sg[0] * h0.x, sg[1] * h0.y, sg[2] * h0.z, sg[3] * h0.w);
            *reinterpret_cast<float4*>(rp + 4) =
                make_float4(sg[4] * h1.x, sg[5] * h1.y, sg[6] * h1.z, sg[7] * h1.w);
        }
    }
}

// ---- k_update — unchanged ----
__global__ void __launch_bounds__(256) k_update(
    const float* __restrict__ whf, const float* __restrict__ whb, int s, int layer1)
{
    const int y0 = blockIdx.x * 2, b = blockIdx.y, dir = blockIdx.z;
    const int t = dir ? (T_ - 1 - s) : s;
    const int frame = b * T_ + t;
    const float* w = dir ? whb : whf;
    __shared__ __align__(16) float s_in[8 * 4 * 35];
    __shared__ __align__(16) float s_w[9 * 8 * 64];
    unsigned long long acc[4 * 2];
    #pragma unroll
    for (int j = 0; j < 8; j++) acc[j] = 0ull;
    conv2core<64, 64>(g_rh[dir] + (size_t)b * HW * 64, 64,
                      w, 64, 192, 0, 128, y0, acc, s_in, s_w);

    const int p = threadIdx.x & 15, g = threadIdx.x >> 4;
    const int row = p >> 3, px0 = (p & 7) * 4;
    #pragma unroll
    for (int i = 0; i < 4; i++) {
        int pixel = (y0 + row) * 32 + px0 + i;
        const float* xgp = g_xg[dir] + ((size_t)frame * HW + pixel) * 192 + 128 + g * 4;
        float4 xv = *reinterpret_cast<const float4*>(xgp);
        float2 a0 = unpk(acc[i * 2 + 0]);
        float2 a1 = unpk(acc[i * 2 + 1]);
        const int pix = (b * HW + pixel) * 64 + g * 4;
        float4 zv = *reinterpret_cast<const float4*>(g_z[dir] + pix);
        float4 hv = *reinterpret_cast<const float4*>(g_h[dir] + pix);
        float hh0 = tanhf(xv.x + a0.x);
        float hh1 = tanhf(xv.y + a0.y);
        float hh2 = tanhf(xv.z + a1.x);
        float hh3 = tanhf(xv.w + a1.y);
        float4 hn = make_float4(zv.x * hv.x + (1.f - zv.x) * hh0,
                                zv.y * hv.y + (1.f - zv.y) * hh1,
                                zv.z * hv.z + (1.f - zv.z) * hh2,
                                zv.w * hv.w + (1.f - zv.w) * hh3);
        *reinterpret_cast<float4*>(g_h[dir] + pix) = hn;
        const size_t opix = ((size_t)frame * HW + pixel) * 128 + dir * 64 + g * 4;
        if (layer1) {
            float4 xo = *reinterpret_cast<const float4*>(g_x0 + opix);
            *reinterpret_cast<float4*>(g_xr + opix) =
                make_float4(xo.x + hn.x, xo.y + hn.y, xo.z + hn.z, xo.w + hn.w);
        } else {
            *reinterpret_cast<float4*>(g_x0 + opix) = hn;
        }
    }
}

// ---- k_final — unchanged ----
__global__ void __launch_bounds__(256) k_final(
    const float* __restrict__ w1, const float* __restrict__ b1,
    const float* __restrict__ wo, const float* __restrict__ bo,
    float* __restrict__ out)
{
    const int y0 = blockIdx.x * 2, n = blockIdx.y;
    __shared__ __align__(16) float s_in[8 * 4 * 35];
    __shared__ __align__(16) float s_w[9 * 8 * 32];
    __shared__ float s_red[16][64];
    unsigned long long acc[4];
    #pragma unroll
    for (int j = 0; j < 4; j++) acc[j] = 0ull;
    conv2core<128, 32>(g_xr + (size_t)n * HW * 128, 128, w1, 256, 32, 0,   0, y0, acc, s_in, s_w);
    conv2core<128, 32>(g_x0 + (size_t)n * HW * 128, 128, w1, 256, 32, 128, 0, y0, acc, s_in, s_w);

    const int p = threadIdx.x & 15, g = threadIdx.x >> 4;
    const int row = p >> 3, px0 = (p & 7) * 4;
    float bb0 = b1[g * 2], bb1 = b1[g * 2 + 1];
    float ww0 = wo[g * 2], ww1 = wo[g * 2 + 1];
    #pragma unroll
    for (int i = 0; i < 4; i++) {
        float2 a = unpk(acc[i]);
        s_red[g][row * 32 + px0 + i] = (a.x + bb0) * ww0 + (a.y + bb1) * ww1;
    }
    __syncthreads();
    if (threadIdx.x < 64) {
        int lp = threadIdx.x;
        float sum = bo[0];
        #pragma unroll
        for (int k = 0; k < 16; k++) sum += s_red[k][lp];
        out[(size_t)n * HW + y0 * 32 + lp] = fmaxf(sum, 0.f);
    }
}

__global__ void k_zero_h()
{
    int i = blockIdx.x * 256 + threadIdx.x;
    if (i < 2 * B_ * HW * F_) (&g_h[0][0])[i] = 0.f;
}

// ============================================================================
// Weight prep: split layer-1 wx into tf32 hi/lo, plain [k][n] tiles per (tap,kc)
// ============================================================================
__global__ void k_prep(const float* __restrict__ wf, const float* __restrict__ wb)
{
    int idx = blockIdx.x * 256 + threadIdx.x;
    if (idx >= (int)(2 * 36 * 6144)) return;
    int s  = idx / (36 * 6144);
    int rm = idx % (36 * 6144);
    int it = rm / 6144, e = rm % 6144;
    int k  = e / 192, nn = e % 192;
    int tap = it >> 2, kc = it & 3;
    const float* w = s ? wb : wf;
    float v = w[((size_t)(tap * 128 + kc * 32 + k)) * 192 + nn];
    uint32_t hi = f2tf(v);
    uint32_t lo = f2tf(v - __uint_as_float(hi));
    float* dst = g_bpre + (size_t)s * SETSZ + (size_t)it * ITSZ;
    dst[e]        = __uint_as_float(hi);
    dst[6144 + e] = __uint_as_float(lo);
}

// ============================================================================
// mma.sync tf32 xg conv for layer 1 (CIN=128, CO=192), 3xTF32 accuracy.
// Block: M=128 px (4 rows), N=96 couts (grid z selects half). 8 warps (4M x 2N),
// warp tile 32x48 -> 2x6 m16n8 tiles. K = 9 taps x 4 chunks x 32.
// smem (floats): A_hi[128][36], A_lo[128][36], B_hi[32][104], B_lo[32][104]
// ============================================================================
#define APAD 36
#define BPAD 104
#define OFF_AHI 0
#define OFF_ALO (128 * APAD)
#define OFF_BHI (2 * 128 * APAD)
#define OFF_BLO (2 * 128 * APAD + 32 * BPAD)
#define SMEM_MMA2 ((2 * 128 * APAD + 2 * 32 * BPAD) * 4)

__global__ void __launch_bounds__(256) k_xg_mma(
    const float* __restrict__ bias, int dir, int set)
{
    extern __shared__ __align__(16) float sm[];
    float* sAh = sm + OFF_AHI;
    float* sAl = sm + OFF_ALO;
    float* sBh = sm + OFF_BHI;
    float* sBl = sm + OFF_BLO;

    const int tid = threadIdx.x;
    const int lane = tid & 31, warp = tid >> 5;
    const int wM = warp & 3, wN = warp >> 1 & 2 ? 0 : 0; // placeholder (fixed below)
    const int wNn = warp >> 2;                            // 0..1
    const int y0 = blockIdx.x;            // 8 blocks x 4 rows
    const int n  = blockIdx.y;
    const int zn = blockIdx.z;            // n-half: couts [zn*96, zn*96+96)
    const int nhalf = zn * 96;
    const float* in = g_x0 + (size_t)n * HW * 128;
    (void)wM; (void)wN;

    const int warpM = warp & 3;           // 0..3 -> M rows [warpM*32, +32)
    const int warpN = warp >> 2;          // 0..1 -> N cols [warpN*48, +48)
    (void)wNn;

    // staging thread mapping
    const int m  = tid >> 1;              // 0..127
    const int kh = tid & 1;               // 16-float half of the 32-cin chunk
    const int mr = m >> 5, mx = m & 31;

    float acc[2][6][4];
    #pragma unroll
    for (int mt = 0; mt < 2; mt++)
        #pragma unroll
        for (int nt = 0; nt < 6; nt++)
            #pragma unroll
            for (int q = 0; q < 4; q++) acc[mt][nt][q] = 0.f;

    for (int tap = 0; tap < 9; tap++) {
        const int gy = y0 * 4 + mr + tap / 3 - 1;
        const int gx = mx + tap % 3 - 1;
        const bool ok = (unsigned)gy < 32u && (unsigned)gx < 32u;
        const int gofs = ok ? (gy * 32 + gx) : 0;
        for (int kc = 0; kc < 4; kc++) {
            // ---- stage A: 128 px x 32 cin, hi/lo tf32 split ----
            const float4* src = reinterpret_cast<const float4*>(
                in + (size_t)gofs * 128 + kc * 32 + kh * 16);
            #pragma unroll
            for (int j = 0; j < 4; j++) {
                float4 v = ok ? src[j] : make_float4(0.f, 0.f, 0.f, 0.f);
                uint4 h, l;
                h.x = f2tf(v.x); l.x = f2tf(v.x - __uint_as_float(h.x));
                h.y = f2tf(v.y); l.y = f2tf(v.y - __uint_as_float(h.y));
                h.z = f2tf(v.z); l.z = f2tf(v.z - __uint_as_float(h.z));
                h.w = f2tf(v.w); l.w = f2tf(v.w - __uint_as_float(h.w));
                int off = m * APAD + kh * 16 + j * 4;
                *reinterpret_cast<uint4*>(sAh + off) = h;
                *reinterpret_cast<uint4*>(sAl + off) = l;
            }
            // ---- stage B: 32 k x 96 n (this block's half), hi/lo ----
            {
                const int it = tap * 4 + kc;
                const float* bsrc = g_bpre + (size_t)set * SETSZ + (size_t)it * ITSZ;
                #pragma unroll
                for (int i = 0; i < 3; i++) {
                    int e  = tid + i * 256;      // 0..767 float4s
                    int k  = e / 24;
                    int n4 = (e % 24) * 4;
                    float4 vh = *reinterpret_cast<const float4*>(
                        bsrc + (size_t)k * 192 + nhalf + n4);
                    float4 vl = *reinterpret_cast<const float4*>(
                        bsrc + 6144 + (size_t)k * 192 + nhalf + n4);
                    *reinterpret_cast<float4*>(sBh + k * BPAD + n4) = vh;
                    *reinterpret_cast<float4*>(sBl + k * BPAD + n4) = vl;
                }
            }
            __syncthreads();

            // ---- compute: 4 k8 steps, 3xTF32 ----
            #pragma unroll
            for (int ks = 0; ks < 4; ks++) {
                const int kb = ks * 8;
                uint32_t aH[2][4], aL[2][4];
                #pragma unroll
                for (int mt = 0; mt < 2; mt++) {
                    int r = warpM * 32 + mt * 16 + (lane >> 2);
                    int c = kb + (lane & 3);
                    aH[mt][0] = __float_as_uint(sAh[r * APAD + c]);
                    aH[mt][1] = __float_as_uint(sAh[(r + 8) * APAD + c]);
                    aH[mt][2] = __float_as_uint(sAh[r * APAD + c + 4]);
                    aH[mt][3] = __float_as_uint(sAh[(r + 8) * APAD + c + 4]);
                    aL[mt][0] = __float_as_uint(sAl[r * APAD + c]);
                    aL[mt][1] = __float_as_uint(sAl[(r + 8) * APAD + c]);
                    aL[mt][2] = __float_as_uint(sAl[r * APAD + c + 4]);
                    aL[mt][3] = __float_as_uint(sAl[(r + 8) * APAD + c + 4]);
                }
                #pragma unroll
                for (int nt = 0; nt < 6; nt++) {
                    int nb = warpN * 48 + nt * 8 + (lane >> 2);
                    int kr = kb + (lane & 3);
                    uint32_t bH0 = __float_as_uint(sBh[kr * BPAD + nb]);
                    uint32_t bH1 = __float_as_uint(sBh[(kr + 4) * BPAD + nb]);
                    uint32_t bL0 = __float_as_uint(sBl[kr * BPAD + nb]);
                    uint32_t bL1 = __float_as_uint(sBl[(kr + 4) * BPAD + nb]);
                    #pragma unroll
                    for (int mt = 0; mt < 2; mt++) {
                        mma8(acc[mt][nt], aH[mt], bH0, bH1);
                        mma8(acc[mt][nt], aH[mt], bL0, bL1);
                        mma8(acc[mt][nt], aL[mt], bH0, bH1);
                    }
                }
            }
            __syncthreads();
        }
    }

    // ---- epilogue: scatter to g_xg with bias ----
    float* xg = g_xg[dir];
    #pragma unroll
    for (int mt = 0; mt < 2; mt++) {
        int r0 = warpM * 32 + mt * 16 + (lane >> 2);
        #pragma unroll
        for (int nt = 0; nt < 6; nt++) {
            int cout = nhalf + warpN * 48 + nt * 8 + (lane & 3) * 2;
            float bb0 = bias[cout], bb1 = bias[cout + 1];
            size_t base0 = ((size_t)n * HW + y0 * 32 * 4 / 4 * 4 + r0);
            // pixel = y0*128 + m  (block covers pixels [y0*128, y0*128+128))
            size_t p0 = ((size_t)n * HW + (size_t)y0 * 128 + r0) * 192 + cout;
            size_t p1 = ((size_t)n * HW + (size_t)y0 * 128 + r0 + 8) * 192 + cout;
            (void)base0;
            *reinterpret_cast<float2*>(xg + p0) =
                make_float2(acc[mt][nt][0] + bb0, acc[mt][nt][1] + bb1);
            *reinterpret_cast<float2*>(xg + p1) =
                make_float2(acc[mt][nt][2] + bb0, acc[mt][nt][3] + bb1);
        }
    }
}

// ============================================================================
extern "C" void kernel_launch(void* const* d_in, const int* in_sizes, int n_in,
                              void* d_out, int out_size)
{
    (void)in_sizes; (void)n_in; (void)out_size;
    const float* x     = (const float*)d_in[0];
    const float* wx_f0 = (const float*)d_in[1];
    const float* wh_f0 = (const float*)d_in[2];
    const float* b_f0  = (const float*)d_in[3];
    const float* wx_b0 = (const float*)d_in[4];
    const float* wh_b0 = (const float*)d_in[5];
    const float* b_b0  = (const float*)d_in[6];
    const float* wx_f1 = (const float*)d_in[7];
    const float* wh_f1 = (const float*)d_in[8];
    const float* b_f1  = (const float*)d_in[9];
    const float* wx_b1 = (const float*)d_in[10];
    const float* wh_b1 = (const float*)d_in[11];
    const float* b_b1  = (const float*)d_in[12];
    const float* w1    = (const float*)d_in[13];
    const float* b1    = (const float*)d_in[14];
    const float* wo    = (const float*)d_in[15];
    const float* bo    = (const float*)d_in[16];
    float* out = (float*)d_out;

    dim3 blk(256);
    cudaFuncSetAttribute(k_xg_mma, cudaFuncAttributeMaxDynamicSharedMemorySize, SMEM_MMA2);

    k_prep<<<(2 * 36 * 6144 + 255) / 256, blk>>>(wx_f1, wx_b1);

    // ---- layer 0 ----
    k_xg<24><<<dim3(16, NF, 3), blk>>>(x, wx_f0, b_f0, 0);
    k_xg<24><<<dim3(16, NF, 3), blk>>>(x, wx_b0, b_b0, 1);
    k_zero_h<<<(2 * B_ * HW * F_ + 255) / 256, blk>>>();
    for (int s = 0; s < T_; s++) {
        k_gate  <<<dim3(16, B_, 2), blk>>>(wh_f0, wh_b0, s);
        k_update<<<dim3(16, B_, 2), blk>>>(wh_f0, wh_b0, s, 0);
    }

    // ---- layer 1: tensor-core (mma.sync tf32 3x) input-gate convs ----
    k_xg_mma<<<dim3(8, NF, 2), blk, SMEM_MMA2>>>(b_f1, 0, 0);
    k_xg_mma<<<dim3(8, NF, 2), blk, SMEM_MMA2>>>(b_b1, 1, 1);
    k_zero_h<<<(2 * B_ * HW * F_ + 255) / 256, blk>>>();
    for (int s = 0; s < T_; s++) {
        k_gate  <<<dim3(16, B_, 2), blk>>>(wh_f1, wh_b1, s);
        k_update<<<dim3(16, B_, 2), blk>>>(wh_f1, wh_b1, s, 1);
    }

    // ---- fused head ----
    k_final<<<dim3(16, NF), blk>>>(w1, b1, wo, bo, out);
}